// round 2
// baseline (speedup 1.0000x reference)
#include <cuda_runtime.h>
#include <cstdint>
#include <cstddef>

#define D 128
#define NVEC 65536                 // 16 * 64 * 64
#define CBT_FLOATS 65280           // 510 * 128
#define OUT_TENSOR 67108864LL      // 8*16*128*64*64

// -------- scratch (static device globals; no runtime allocation) --------
__device__ float g_cbT[CBT_FLOATS];          // channel-major per level: cbT[c*sz + j]
__device__ float g_cbJ[CBT_FLOATS];          // codeword-major: cbJ[k*128 + c]
__device__ float g_cnorm[768];               // ||c||^2, padded per level
__device__ unsigned long long g_idx[NVEC];   // 8 packed uint8 indices per vector
__device__ float g_lsum[8];                  // per-level sum of min distances

// stage s (0-based) uses weight rows c_rows[2s], c_rows[2s+1]
__constant__ int c_rows[16] = {0,1, 3,4, 4,5, 5,6, 6,7, 7,8, 8,9, 9,10};
__constant__ int c_pad[8] = {0, 4, 8, 16, 48, 112, 240, 496};
__constant__ float c_coef[8] = {1.5f, 1.2f, 1.0f, 0.9f, 0.82f, 0.69f, 0.65f, 0.56f};

// ---------------------------------------------------------------------------
// Kernel 0: build both codebook layouts + squared norms; zero loss accums.
// ---------------------------------------------------------------------------
__global__ void build_kernel(const float* __restrict__ w) {
    int k  = blockIdx.x;              // 0..509 global codeword id
    int li = 30 - __clz(k + 2);       // level index 0..7
    int L  = li + 1;
    int sz = 1 << L;
    int j  = k - (sz - 2);            // codeword index within level
    int c  = threadIdx.x;             // channel 0..127

    float val = 0.f;
    for (int s = 0; s < L; s++) {
        int bit = (j >> (L - 1 - s)) & 1;
        val += w[c_rows[2 * s + bit] * D + c];
    }
    g_cbT[(sz - 2) * D + c * sz + j] = val;
    g_cbJ[k * D + c] = val;

    __shared__ float red[128];
    red[c] = val * val;
    __syncthreads();
    #pragma unroll
    for (int o = 64; o > 0; o >>= 1) {
        if (c < o) red[c] += red[c + o];
        __syncthreads();
    }
    if (c == 0) g_cnorm[c_pad[li] + j] = red[0];

    if (blockIdx.x == 0 && c < 8) g_lsum[c] = 0.f;   // reset each launch
}

// ---------------------------------------------------------------------------
// Kernel 1: per-vector quantization (unchanged from passing version).
// ---------------------------------------------------------------------------
__global__ void __launch_bounds__(256, 2)
quant_kernel(const float* __restrict__ inp, const float* __restrict__ w) {
    __shared__ float s_bv[16][128];   // base vectors pre-scaled by -2
    __shared__ float sC[768];
    __shared__ float s_loss[8];

    int tid = threadIdx.x;
    for (int i = tid; i < 16 * 128; i += 256) {
        int s = i >> 7, c = i & 127;
        s_bv[s][c] = -2.0f * w[c_rows[s] * D + c];
    }
    for (int i = tid; i < 752; i += 256) sC[i] = g_cnorm[i];
    if (tid < 8) s_loss[tid] = 0.f;
    __syncthreads();

    int vec = blockIdx.x * 256 + tid;                     // 0..65535
    const float* xp = inp + ((size_t)(vec >> 12) << 19) + (vec & 4095);

    float acc[16];
    #pragma unroll
    for (int s = 0; s < 16; s++) acc[s] = 0.f;
    float xn = 0.f;

    #pragma unroll 4
    for (int c4 = 0; c4 < 32; c4++) {
        float x0 = xp[(4 * c4 + 0) * 4096];
        float x1 = xp[(4 * c4 + 1) * 4096];
        float x2 = xp[(4 * c4 + 2) * 4096];
        float x3 = xp[(4 * c4 + 3) * 4096];
        xn = fmaf(x0, x0, xn); xn = fmaf(x1, x1, xn);
        xn = fmaf(x2, x2, xn); xn = fmaf(x3, x3, xn);
        #pragma unroll
        for (int s = 0; s < 16; s++) {
            float4 bq = reinterpret_cast<const float4*>(&s_bv[s][0])[c4];
            acc[s] = fmaf(x0, bq.x, acc[s]);
            acc[s] = fmaf(x1, bq.y, acc[s]);
            acc[s] = fmaf(x2, bq.z, acc[s]);
            acc[s] = fmaf(x3, bq.w, acc[s]);
        }
    }

    float* p = acc;

    float A2[4], A3[8], A4[16], B2[4], B3[8], B4[16];
    #pragma unroll
    for (int j = 0; j < 4;  j++) A2[j] = p[j >> 1] + p[2 + (j & 1)];
    #pragma unroll
    for (int j = 0; j < 8;  j++) A3[j] = A2[j >> 1] + p[4 + (j & 1)];
    #pragma unroll
    for (int j = 0; j < 16; j++) A4[j] = A3[j >> 1] + p[6 + (j & 1)];
    #pragma unroll
    for (int j = 0; j < 4;  j++) B2[j] = p[8 + (j >> 1)] + p[10 + (j & 1)];
    #pragma unroll
    for (int j = 0; j < 8;  j++) B3[j] = B2[j >> 1] + p[12 + (j & 1)];
    #pragma unroll
    for (int j = 0; j < 16; j++) B4[j] = B3[j >> 1] + p[14 + (j & 1)];

    const float INF = __int_as_float(0x7f800000);
    float m[8]; int mi[8];
    #pragma unroll
    for (int l = 0; l < 8; l++) { m[l] = INF; mi[l] = 0; }

    #pragma unroll
    for (int j = 0; j < 2;   j++) { float s = p[j]            + sC[0   + j]; if (s < m[0]) { m[0] = s; mi[0] = j; } }
    #pragma unroll
    for (int j = 0; j < 4;   j++) { float s = A2[j]           + sC[4   + j]; if (s < m[1]) { m[1] = s; mi[1] = j; } }
    #pragma unroll
    for (int j = 0; j < 8;   j++) { float s = A3[j]           + sC[8   + j]; if (s < m[2]) { m[2] = s; mi[2] = j; } }
    #pragma unroll
    for (int j = 0; j < 16;  j++) { float s = A4[j]           + sC[16  + j]; if (s < m[3]) { m[3] = s; mi[3] = j; } }
    #pragma unroll
    for (int j = 0; j < 32;  j++) { float s = A4[j >> 1] + p[8 + (j & 1)]  + sC[48  + j]; if (s < m[4]) { m[4] = s; mi[4] = j; } }
    #pragma unroll
    for (int j = 0; j < 64;  j++) { float s = A4[j >> 2] + B2[j & 3]       + sC[112 + j]; if (s < m[5]) { m[5] = s; mi[5] = j; } }
    #pragma unroll
    for (int j = 0; j < 128; j++) { float s = A4[j >> 3] + B3[j & 7]       + sC[240 + j]; if (s < m[6]) { m[6] = s; mi[6] = j; } }
    #pragma unroll
    for (int j = 0; j < 256; j++) { float s = A4[j >> 4] + B4[j & 15]      + sC[496 + j]; if (s < m[7]) { m[7] = s; mi[7] = j; } }

    unsigned long long pk = 0;
    #pragma unroll
    for (int l = 0; l < 8; l++) pk |= ((unsigned long long)(unsigned)mi[l]) << (8 * l);
    g_idx[vec] = pk;

    int lane = tid & 31;
    #pragma unroll
    for (int l = 0; l < 8; l++) {
        float v = xn + m[l];
        #pragma unroll
        for (int o = 16; o; o >>= 1) v += __shfl_xor_sync(0xffffffffu, v, o);
        if (lane == 0) atomicAdd(&s_loss[l], v);
    }
    __syncthreads();
    if (tid < 8) atomicAdd(&g_lsum[tid], s_loss[tid]);
}

// ---------------------------------------------------------------------------
// Kernel 2: output writer + loss finalize.
// Grid 512 = (8 levels x 16 batches x 4 channel-quarters), heavy levels first.
//  sz >= 128: codeword-major smem, XOR-swizzled float4 slots, LDS.128 gather
//             + 4x4 register transpose -> 4 coalesced STG.128 per quad.
//  sz <  128: channel-major smem, scalar gather (conflict-free for sz<=32).
// ---------------------------------------------------------------------------
__global__ void __launch_bounds__(256)
scatter_kernel(float* __restrict__ out) {
    __shared__ float   scb[8192];    // 32 KB codebook slice
    __shared__ uint8_t sidx[4096];   // this batch's indices for this level

    int bid   = blockIdx.x;
    int level = 7 - (bid >> 6);      // heavy levels scheduled first
    int b     = (bid >> 2) & 15;
    int q     = bid & 3;             // channel quarter (32 channels)
    int sz    = 2 << level;
    int tid   = threadIdx.x;

    if (bid == 0 && tid < 8)         // g_lsum complete after quant launch
        out[OUT_TENSOR + tid] = (c_coef[tid] + 0.4f) * g_lsum[tid] * (1.0f / 8388608.0f);

    bool vecpath = (sz >= 128);
    if (vecpath) {
        int base_k = sz - 2;
        for (int u = tid; u < sz * 8; u += 256) {
            int j = u >> 3, cq = u & 7;
            float4 v = *reinterpret_cast<const float4*>(
                g_cbJ + (size_t)(base_k + j) * 128 + q * 32 + cq * 4);
            *reinterpret_cast<float4*>(scb + j * 32 + ((cq ^ (j & 7)) << 2)) = v;
        }
    } else {
        const float* src = g_cbT + ((sz - 2) << 7) + (q * 32) * sz;
        for (int i = tid; i < 32 * sz; i += 256) scb[i] = src[i];
    }
    const unsigned long long* gi = g_idx + ((size_t)b << 12);
    int sh = level << 3;
    for (int i = tid; i < 4096; i += 256) sidx[i] = (uint8_t)(gi[i] >> sh);
    __syncthreads();

    // output base for (level, b, channel q*32, hw 0)
    float* ob = out + (((size_t)((level << 4) + b) << 7) + ((size_t)q << 5)) * 4096;

    if (vecpath) {
        #pragma unroll
        for (int g = 0; g < 4; g++) {
            int hb = 1024 * g + 4 * tid;            // hw quad base
            int o0 = sidx[hb + 0], o1 = sidx[hb + 1];
            int o2 = sidx[hb + 2], o3 = sidx[hb + 3];
            #pragma unroll
            for (int cq = 0; cq < 8; cq++) {
                float4 a0 = *reinterpret_cast<const float4*>(scb + o0 * 32 + ((cq ^ (o0 & 7)) << 2));
                float4 a1 = *reinterpret_cast<const float4*>(scb + o1 * 32 + ((cq ^ (o1 & 7)) << 2));
                float4 a2 = *reinterpret_cast<const float4*>(scb + o2 * 32 + ((cq ^ (o2 & 7)) << 2));
                float4 a3 = *reinterpret_cast<const float4*>(scb + o3 * 32 + ((cq ^ (o3 & 7)) << 2));
                float* p = ob + (size_t)(cq * 4) * 4096 + hb;
                __stcs(reinterpret_cast<float4*>(p),          make_float4(a0.x, a1.x, a2.x, a3.x));
                __stcs(reinterpret_cast<float4*>(p + 4096),   make_float4(a0.y, a1.y, a2.y, a3.y));
                __stcs(reinterpret_cast<float4*>(p + 8192),   make_float4(a0.z, a1.z, a2.z, a3.z));
                __stcs(reinterpret_cast<float4*>(p + 12288),  make_float4(a0.w, a1.w, a2.w, a3.w));
            }
        }
    } else {
        int o[16];
        #pragma unroll
        for (int g = 0; g < 4; g++) {
            int hb = 1024 * g + 4 * tid;
            o[4 * g + 0] = sidx[hb + 0]; o[4 * g + 1] = sidx[hb + 1];
            o[4 * g + 2] = sidx[hb + 2]; o[4 * g + 3] = sidx[hb + 3];
        }
        for (int c = 0; c < 32; c++) {
            const float* row = scb + c * sz;
            float* oc = ob + (size_t)c * 4096;
            #pragma unroll
            for (int g = 0; g < 4; g++) {
                float4 v = make_float4(row[o[4*g+0]], row[o[4*g+1]],
                                       row[o[4*g+2]], row[o[4*g+3]]);
                __stcs(reinterpret_cast<float4*>(oc + 1024 * g + 4 * tid), v);
            }
        }
    }
}

// ---------------------------------------------------------------------------
extern "C" void kernel_launch(void* const* d_in, const int* in_sizes, int n_in,
                              void* d_out, int out_size) {
    const float* inp = (const float*)d_in[0];   // (16,128,64,64) f32
    const float* w   = (const float*)d_in[1];   // (256,128) f32
    float* out       = (float*)d_out;

    (void)in_sizes; (void)n_in; (void)out_size;

    build_kernel<<<510, 128>>>(w);
    quant_kernel<<<256, 256>>>(inp, w);
    scatter_kernel<<<512, 256>>>(out);
}

// round 3
// speedup vs baseline: 1.0305x; 1.0305x over previous
#include <cuda_runtime.h>
#include <cstdint>
#include <cstddef>

#define D 128
#define NVEC 65536                 // 16 * 64 * 64
#define CBT_FLOATS 65280           // 510 * 128
#define OUT_TENSOR 67108864LL      // 8*16*128*64*64

// -------- scratch (static device globals; no runtime allocation) --------
__device__ float g_cbT[CBT_FLOATS];          // channel-major per level: cbT[c*sz + j]
__device__ float g_cbJ[CBT_FLOATS];          // codeword-major: cbJ[k*128 + c]
__device__ float g_cnorm[768];               // ||c||^2, padded per level
__device__ unsigned long long g_idx[NVEC];   // 8 packed uint8 indices per vector
__device__ float g_lsum[8];                  // per-level sum of min distances

// stage s (0-based) uses weight rows c_rows[2s], c_rows[2s+1]
__constant__ int c_rows[16] = {0,1, 3,4, 4,5, 5,6, 6,7, 7,8, 8,9, 9,10};
__constant__ int c_rl[10]   = {0, 1, 3, 4, 5, 6, 7, 8, 9, 10};   // distinct rows
__constant__ int c_pad[8] = {0, 4, 8, 16, 48, 112, 240, 496};
__constant__ float c_coef[8] = {1.5f, 1.2f, 1.0f, 0.9f, 0.82f, 0.69f, 0.65f, 0.56f};

__device__ __forceinline__ void pdl_wait()    { asm volatile("griddepcontrol.wait;" ::: "memory"); }
__device__ __forceinline__ void pdl_trigger() { asm volatile("griddepcontrol.launch_dependents;"); }

__device__ __forceinline__ void ffma2(unsigned long long& d,
                                      unsigned long long a, unsigned long long b) {
    asm("fma.rn.f32x2 %0, %1, %2, %0;" : "+l"(d) : "l"(a), "l"(b));
}
__device__ __forceinline__ void unpack2(unsigned long long v, float& lo, float& hi) {
    asm("mov.b64 {%0, %1}, %2;" : "=f"(lo), "=f"(hi) : "l"(v));
}

// ---------------------------------------------------------------------------
// Kernel 0: build both codebook layouts + squared norms; zero loss accums.
// ---------------------------------------------------------------------------
__global__ void build_kernel(const float* __restrict__ w) {
    int k  = blockIdx.x;              // 0..509 global codeword id
    int li = 30 - __clz(k + 2);       // level index 0..7
    int L  = li + 1;
    int sz = 1 << L;
    int j  = k - (sz - 2);            // codeword index within level
    int c  = threadIdx.x;             // channel 0..127

    float val = 0.f;
    #pragma unroll 8
    for (int s = 0; s < L; s++) {
        int bit = (j >> (L - 1 - s)) & 1;
        val += w[c_rows[2 * s + bit] * D + c];
    }
    g_cbT[(sz - 2) * D + c * sz + j] = val;
    g_cbJ[k * D + c] = val;

    float v2 = val * val;
    #pragma unroll
    for (int o = 16; o; o >>= 1) v2 += __shfl_xor_sync(0xffffffffu, v2, o);
    __shared__ float part[4];
    if ((c & 31) == 0) part[c >> 5] = v2;
    __syncthreads();
    if (c == 0) g_cnorm[c_pad[li] + j] = part[0] + part[1] + part[2] + part[3];

    if (blockIdx.x == 0 && c < 8) g_lsum[c] = 0.f;   // reset each launch
    pdl_trigger();
}

// ---------------------------------------------------------------------------
// Kernel 1: per-vector quantization.
// Only 10 distinct weight rows feed the 16 stage vectors -> 10 dots, done
// as 5 packed fma.rn.f32x2 chains. Prefix trees + strict-< argmin unchanged.
// ---------------------------------------------------------------------------
__global__ void __launch_bounds__(256, 2)
quant_kernel(const float* __restrict__ inp, const float* __restrict__ w) {
    __shared__ __align__(16) float s_bvp[128][12];   // per channel: 10 rows *(-2), pad 2
    __shared__ float sC[768];
    __shared__ float s_loss[8];

    int tid = threadIdx.x;
    // prelude independent of build output:
    for (int i = tid; i < 1280; i += 256) {
        int c = i & 127, t = i >> 7;
        s_bvp[c][t] = -2.0f * w[c_rl[t] * D + c];
    }
    { int c = tid & 127, t = tid >> 7; s_bvp[c][10 + t] = 0.f; }
    if (tid < 8) s_loss[tid] = 0.f;

    pdl_wait();   // build's g_cnorm must be visible below
    for (int i = tid; i < 752; i += 256) sC[i] = g_cnorm[i];
    __syncthreads();

    int vec = blockIdx.x * 256 + tid;                     // 0..65535
    const float* xp = inp + ((size_t)(vec >> 12) << 19) + (vec & 4095);

    unsigned long long a01 = 0, a34 = 0, a56 = 0, a78 = 0, a910 = 0;
    float xn = 0.f;

    #pragma unroll 8
    for (int c = 0; c < 128; c++) {
        float x = xp[c * 4096];
        unsigned long long xx;
        asm("mov.b64 %0, {%1, %1};" : "=l"(xx) : "f"(x));
        const ulonglong2* bp = reinterpret_cast<const ulonglong2*>(&s_bvp[c][0]);
        ulonglong2 P0 = bp[0];
        ulonglong2 P1 = bp[1];
        unsigned long long P2 = reinterpret_cast<const unsigned long long*>(&s_bvp[c][0])[4];
        ffma2(a01,  xx, P0.x);
        ffma2(a34,  xx, P0.y);
        ffma2(a56,  xx, P1.x);
        ffma2(a78,  xx, P1.y);
        ffma2(a910, xx, P2);
        xn = fmaf(x, x, xn);
    }

    float d0, d1, d3, d4, d5, d6, d7, d8, d9, d10;
    unpack2(a01,  d0, d1);
    unpack2(a34,  d3, d4);
    unpack2(a56,  d5, d6);
    unpack2(a78,  d7, d8);
    unpack2(a910, d9, d10);

    // p[2s+b] = -2 x . v_{s,b}  (stage rows: (0,1)(3,4)(4,5)(5,6)(6,7)(7,8)(8,9)(9,10))
    float p[16] = {d0, d1, d3, d4, d4, d5, d5, d6, d6, d7, d7, d8, d8, d9, d9, d10};

    float A2[4], A3[8], A4[16], B2[4], B3[8], B4[16];
    #pragma unroll
    for (int j = 0; j < 4;  j++) A2[j] = p[j >> 1] + p[2 + (j & 1)];
    #pragma unroll
    for (int j = 0; j < 8;  j++) A3[j] = A2[j >> 1] + p[4 + (j & 1)];
    #pragma unroll
    for (int j = 0; j < 16; j++) A4[j] = A3[j >> 1] + p[6 + (j & 1)];
    #pragma unroll
    for (int j = 0; j < 4;  j++) B2[j] = p[8 + (j >> 1)] + p[10 + (j & 1)];
    #pragma unroll
    for (int j = 0; j < 8;  j++) B3[j] = B2[j >> 1] + p[12 + (j & 1)];
    #pragma unroll
    for (int j = 0; j < 16; j++) B4[j] = B3[j >> 1] + p[14 + (j & 1)];

    const float INF = __int_as_float(0x7f800000);
    float m[8]; int mi[8];
    #pragma unroll
    for (int l = 0; l < 8; l++) { m[l] = INF; mi[l] = 0; }

    // strict '<' keeps the FIRST minimum (matches jnp.argmin tie-break)
    #pragma unroll
    for (int j = 0; j < 2;   j++) { float s = p[j]            + sC[0   + j]; if (s < m[0]) { m[0] = s; mi[0] = j; } }
    #pragma unroll
    for (int j = 0; j < 4;   j++) { float s = A2[j]           + sC[4   + j]; if (s < m[1]) { m[1] = s; mi[1] = j; } }
    #pragma unroll
    for (int j = 0; j < 8;   j++) { float s = A3[j]           + sC[8   + j]; if (s < m[2]) { m[2] = s; mi[2] = j; } }
    #pragma unroll
    for (int j = 0; j < 16;  j++) { float s = A4[j]           + sC[16  + j]; if (s < m[3]) { m[3] = s; mi[3] = j; } }
    #pragma unroll
    for (int j = 0; j < 32;  j++) { float s = A4[j >> 1] + p[8 + (j & 1)]  + sC[48  + j]; if (s < m[4]) { m[4] = s; mi[4] = j; } }
    #pragma unroll
    for (int j = 0; j < 64;  j++) { float s = A4[j >> 2] + B2[j & 3]       + sC[112 + j]; if (s < m[5]) { m[5] = s; mi[5] = j; } }
    #pragma unroll
    for (int j = 0; j < 128; j++) { float s = A4[j >> 3] + B3[j & 7]       + sC[240 + j]; if (s < m[6]) { m[6] = s; mi[6] = j; } }
    #pragma unroll
    for (int j = 0; j < 256; j++) { float s = A4[j >> 4] + B4[j & 15]      + sC[496 + j]; if (s < m[7]) { m[7] = s; mi[7] = j; } }

    unsigned long long pk = 0;
    #pragma unroll
    for (int l = 0; l < 8; l++) pk |= ((unsigned long long)(unsigned)mi[l]) << (8 * l);
    g_idx[vec] = pk;

    int lane = tid & 31;
    #pragma unroll
    for (int l = 0; l < 8; l++) {
        float v = xn + m[l];
        #pragma unroll
        for (int o = 16; o; o >>= 1) v += __shfl_xor_sync(0xffffffffu, v, o);
        if (lane == 0) atomicAdd(&s_loss[l], v);
    }
    __syncthreads();
    if (tid < 8) atomicAdd(&g_lsum[tid], s_loss[tid]);
    pdl_trigger();
}

// ---------------------------------------------------------------------------
// Kernel 2: output writer + loss finalize.
// 1024 tiles = (8 levels x 16 batches x 4 channel-quarters x 2 hw-halves),
// heavy levels first (tail granularity ~1%).
//  sz >= 64 : codeword-major smem, XOR-swizzled float4 slots, LDS.128 gather
//             + 4x4 register transpose -> coalesced STG.128.
//  sz <= 32 : channel-major smem, conflict-free scalar gather.
// Codebook smem load happens BEFORE the PDL wait (depends only on build).
// ---------------------------------------------------------------------------
__global__ void __launch_bounds__(256)
scatter_kernel(float* __restrict__ out) {
    __shared__ __align__(16) float scb[8192];    // 32 KB codebook slice
    __shared__ uint8_t sidx[2048];               // indices for this hw-half

    int bid   = blockIdx.x;
    int level = 7 - (bid >> 7);      // heavy levels scheduled first
    int r     = bid & 127;
    int b     = r >> 3;              // 0..15
    int q     = (r >> 1) & 3;        // channel quarter (32 channels)
    int h     = r & 1;               // hw half (2048 positions)
    int sz    = 2 << level;
    int tid   = threadIdx.x;

    bool vecpath = (sz >= 64);
    if (vecpath) {
        int base_k = sz - 2;
        for (int u = tid; u < sz * 8; u += 256) {
            int j = u >> 3, cq = u & 7;
            float4 v = *reinterpret_cast<const float4*>(
                g_cbJ + (size_t)(base_k + j) * 128 + q * 32 + cq * 4);
            *reinterpret_cast<float4*>(scb + j * 32 + ((cq ^ (j & 7)) << 2)) = v;
        }
    } else {
        const float* src = g_cbT + ((sz - 2) << 7) + (q * 32) * sz;
        for (int i = tid; i < 32 * sz; i += 256) scb[i] = src[i];
    }

    pdl_wait();   // quant's g_idx / g_lsum must be visible below

    if (bid == 0 && tid < 8)
        out[OUT_TENSOR + tid] = (c_coef[tid] + 0.4f) * g_lsum[tid] * (1.0f / 8388608.0f);

    const unsigned long long* gi = g_idx + ((size_t)b << 12) + (h << 11);
    int sh = level << 3;
    for (int i = tid; i < 2048; i += 256) sidx[i] = (uint8_t)(gi[i] >> sh);
    __syncthreads();

    // output base for (level, b, channel q*32, hw-half h)
    float* obh = out + (((size_t)((level << 4) + b) << 7) + ((size_t)q << 5)) * 4096
                     + ((size_t)h << 11);

    if (vecpath) {
        #pragma unroll
        for (int g = 0; g < 2; g++) {
            int hb = 1024 * g + 4 * tid;            // hw quad base within half
            int o0 = sidx[hb + 0], o1 = sidx[hb + 1];
            int o2 = sidx[hb + 2], o3 = sidx[hb + 3];
            #pragma unroll
            for (int cq = 0; cq < 8; cq++) {
                float4 a0 = *reinterpret_cast<const float4*>(scb + o0 * 32 + ((cq ^ (o0 & 7)) << 2));
                float4 a1 = *reinterpret_cast<const float4*>(scb + o1 * 32 + ((cq ^ (o1 & 7)) << 2));
                float4 a2 = *reinterpret_cast<const float4*>(scb + o2 * 32 + ((cq ^ (o2 & 7)) << 2));
                float4 a3 = *reinterpret_cast<const float4*>(scb + o3 * 32 + ((cq ^ (o3 & 7)) << 2));
                float* p = obh + (size_t)(cq * 4) * 4096 + hb;
                *reinterpret_cast<float4*>(p)         = make_float4(a0.x, a1.x, a2.x, a3.x);
                *reinterpret_cast<float4*>(p + 4096)  = make_float4(a0.y, a1.y, a2.y, a3.y);
                *reinterpret_cast<float4*>(p + 8192)  = make_float4(a0.z, a1.z, a2.z, a3.z);
                *reinterpret_cast<float4*>(p + 12288) = make_float4(a0.w, a1.w, a2.w, a3.w);
            }
        }
    } else {
        int o[8];
        #pragma unroll
        for (int g = 0; g < 2; g++) {
            int hb = 1024 * g + 4 * tid;
            o[4 * g + 0] = sidx[hb + 0]; o[4 * g + 1] = sidx[hb + 1];
            o[4 * g + 2] = sidx[hb + 2]; o[4 * g + 3] = sidx[hb + 3];
        }
        for (int c = 0; c < 32; c++) {
            const float* row = scb + c * sz;
            float* oc = obh + (size_t)c * 4096;
            #pragma unroll
            for (int g = 0; g < 2; g++) {
                float4 v = make_float4(row[o[4*g+0]], row[o[4*g+1]],
                                       row[o[4*g+2]], row[o[4*g+3]]);
                *reinterpret_cast<float4*>(oc + 1024 * g + 4 * tid) = v;
            }
        }
    }
}

// ---------------------------------------------------------------------------
extern "C" void kernel_launch(void* const* d_in, const int* in_sizes, int n_in,
                              void* d_out, int out_size) {
    const float* inp = (const float*)d_in[0];   // (16,128,64,64) f32
    const float* w   = (const float*)d_in[1];   // (256,128) f32
    float* out       = (float*)d_out;

    (void)in_sizes; (void)n_in; (void)out_size;

    build_kernel<<<510, 128>>>(w);

    cudaLaunchAttribute at[1];
    at[0].id = cudaLaunchAttributeProgrammaticStreamSerialization;
    at[0].val.programmaticStreamSerializationAllowed = 1;

    cudaLaunchConfig_t cfg = {};
    cfg.blockDim = dim3(256, 1, 1);
    cfg.dynamicSmemBytes = 0;
    cfg.stream = 0;
    cfg.attrs = at;
    cfg.numAttrs = 1;

    cfg.gridDim = dim3(256, 1, 1);
    if (cudaLaunchKernelEx(&cfg, quant_kernel, inp, w) != cudaSuccess)
        quant_kernel<<<256, 256>>>(inp, w);

    cfg.gridDim = dim3(1024, 1, 1);
    if (cudaLaunchKernelEx(&cfg, scatter_kernel, out) != cudaSuccess)
        scatter_kernel<<<1024, 256>>>(out);
}